// round 1
// baseline (speedup 1.0000x reference)
#include <cuda_runtime.h>
#include <math.h>

#define W_IMG 1024
#define N_PIX (W_IMG * W_IMG)
#define TX 32          // tile width
#define TILE_Y 32      // tile height
#define RPT 4          // rows per thread
#define NTH 256        // threads per block (32 x 8 warps)
#define HX 34          // halo tile width
#define HY 34          // halo tile height
#define HPIX (HX * HY)
#define MAXB 8

// stats per batch: [0..2]=sum q_c^2, [3..5]=sum k_c^2, [6..14]=sum q_c*k_d
__device__ float g_stats[MAXB][16];
__device__ float g_M[MAXB][12];

__global__ void k_zero() {
    int i = threadIdx.x;
    if (i < MAXB * 16) ((float*)g_stats)[i] = 0.0f;
}

// conv1x1 of a planar [3][1024][1024] input into smem halo tile (zero-padded)
__device__ __forceinline__ void stage1_planar(const float* __restrict__ in,
                                              const float* __restrict__ Cw,
                                              float (*s)[HY][HX],
                                              int gx0, int gy0, int tid) {
    const float c00 = Cw[0], c01 = Cw[1], c02 = Cw[2],
                c10 = Cw[3], c11 = Cw[4], c12 = Cw[5],
                c20 = Cw[6], c21 = Cw[7], c22 = Cw[8];
    for (int idx = tid; idx < HPIX; idx += NTH) {
        int ly = idx / HX, lx = idx - ly * HX;
        int gy = gy0 + ly - 1, gx = gx0 + lx - 1;
        float r0 = 0.f, r1 = 0.f, r2 = 0.f;
        if ((unsigned)gy < (unsigned)W_IMG && (unsigned)gx < (unsigned)W_IMG) {
            int o = gy * W_IMG + gx;
            float f0 = in[o], f1 = in[o + N_PIX], f2 = in[o + 2 * N_PIX];
            r0 = c00 * f0 + c01 * f1 + c02 * f2;
            r1 = c10 * f0 + c11 * f1 + c12 * f2;
            r2 = c20 * f0 + c21 * f1 + c22 * f2;
        }
        s[0][ly][lx] = r0;
        s[1][ly][lx] = r1;
        s[2][ly][lx] = r2;
    }
}

// conv1x1 of channels-last [N][3] input into smem halo tile (zero-padded)
__device__ __forceinline__ void stage1_chanlast(const float* __restrict__ in,
                                                const float* __restrict__ Cw,
                                                float (*s)[HY][HX],
                                                int gx0, int gy0, int tid) {
    const float c00 = Cw[0], c01 = Cw[1], c02 = Cw[2],
                c10 = Cw[3], c11 = Cw[4], c12 = Cw[5],
                c20 = Cw[6], c21 = Cw[7], c22 = Cw[8];
    for (int idx = tid; idx < HPIX; idx += NTH) {
        int ly = idx / HX, lx = idx - ly * HX;
        int gy = gy0 + ly - 1, gx = gx0 + lx - 1;
        float r0 = 0.f, r1 = 0.f, r2 = 0.f;
        if ((unsigned)gy < (unsigned)W_IMG && (unsigned)gx < (unsigned)W_IMG) {
            int o = (gy * W_IMG + gx) * 3;
            float f0 = in[o], f1 = in[o + 1], f2 = in[o + 2];
            r0 = c00 * f0 + c01 * f1 + c02 * f2;
            r1 = c10 * f0 + c11 * f1 + c12 * f2;
            r2 = c20 * f0 + c21 * f1 + c22 * f2;
        }
        s[0][ly][lx] = r0;
        s[1][ly][lx] = r1;
        s[2][ly][lx] = r2;
    }
}

// depthwise 3x3 over a 4-row output column; sliding 6-row x 3-col window
__device__ __forceinline__ void dw_col(const float (*s)[HY][HX],
                                       const float* __restrict__ Dw,
                                       int tx, int oy0, float out[3][RPT]) {
#pragma unroll
    for (int c = 0; c < 3; c++) {
        float w[9];
#pragma unroll
        for (int i = 0; i < 9; i++) w[i] = Dw[c * 9 + i];
        float o0 = 0.f, o1 = 0.f, o2 = 0.f, o3 = 0.f;
#pragma unroll
        for (int r = 0; r < 6; r++) {
            float a = s[c][oy0 + r][tx];
            float bm = s[c][oy0 + r][tx + 1];
            float cc = s[c][oy0 + r][tx + 2];
            if (r <= 2) { int q = r;     o0 += w[q*3]*a + w[q*3+1]*bm + w[q*3+2]*cc; }
            if (r >= 1 && r <= 3) { int q = r - 1; o1 += w[q*3]*a + w[q*3+1]*bm + w[q*3+2]*cc; }
            if (r >= 2 && r <= 4) { int q = r - 2; o2 += w[q*3]*a + w[q*3+1]*bm + w[q*3+2]*cc; }
            if (r >= 3) { int q = r - 3; o3 += w[q*3]*a + w[q*3+1]*bm + w[q*3+2]*cc; }
        }
        out[c][0] = o0; out[c][1] = o1; out[c][2] = o2; out[c][3] = o3;
    }
}

__global__ __launch_bounds__(NTH) void k_stats(const float* __restrict__ x,
                                               const float* __restrict__ fhigh,
                                               const float* __restrict__ qC,
                                               const float* __restrict__ qD,
                                               const float* __restrict__ kC,
                                               const float* __restrict__ kD) {
    __shared__ float s[3][HY][HX];
    __shared__ float red[NTH / 32][15];

    const int b = blockIdx.z;
    const int gx0 = blockIdx.x * TX, gy0 = blockIdx.y * TILE_Y;
    const int tid = threadIdx.x;
    const int tx = tid & 31, tg = tid >> 5;
    const int oy0 = tg * RPT;

    const float* fb = fhigh + (size_t)b * 3 * N_PIX;
    const float* xb = x + (size_t)b * 3 * N_PIX;

    float q[3][RPT], k[3][RPT];

    stage1_planar(fb, qC, s, gx0, gy0, tid);
    __syncthreads();
    dw_col(s, qD, tx, oy0, q);
    __syncthreads();
    stage1_chanlast(xb, kC, s, gx0, gy0, tid);
    __syncthreads();
    dw_col(s, kD, tx, oy0, k);

    float p[15];
#pragma unroll
    for (int i = 0; i < 15; i++) p[i] = 0.f;
#pragma unroll
    for (int r = 0; r < RPT; r++) {
        p[0] += q[0][r] * q[0][r];
        p[1] += q[1][r] * q[1][r];
        p[2] += q[2][r] * q[2][r];
        p[3] += k[0][r] * k[0][r];
        p[4] += k[1][r] * k[1][r];
        p[5] += k[2][r] * k[2][r];
#pragma unroll
        for (int c = 0; c < 3; c++)
#pragma unroll
            for (int d = 0; d < 3; d++)
                p[6 + c * 3 + d] += q[c][r] * k[d][r];
    }
    // warp reduce
#pragma unroll
    for (int i = 0; i < 15; i++)
#pragma unroll
        for (int o = 16; o; o >>= 1)
            p[i] += __shfl_down_sync(0xffffffffu, p[i], o);
    if (tx == 0) {
#pragma unroll
        for (int i = 0; i < 15; i++) red[tg][i] = p[i];
    }
    __syncthreads();
    if (tid < 15) {
        float t = 0.f;
#pragma unroll
        for (int w2 = 0; w2 < NTH / 32; w2++) t += red[w2][tid];
        atomicAdd(&g_stats[b][tid], t);
    }
}

__global__ void k_attn(const float* __restrict__ proj_w,
                       const float* __restrict__ temp, int B) {
    if (threadIdx.x != 0 || blockIdx.x != 0) return;
    float T = temp[0];
    for (int b = 0; b < B; b++) {
        float nq[3], nk[3];
#pragma unroll
        for (int c = 0; c < 3; c++) {
            nq[c] = fmaxf(sqrtf(g_stats[b][c]), 1e-12f);
            nk[c] = fmaxf(sqrtf(g_stats[b][3 + c]), 1e-12f);
        }
        float a[3][3];
#pragma unroll
        for (int c = 0; c < 3; c++)
#pragma unroll
            for (int d = 0; d < 3; d++)
                a[c][d] = g_stats[b][6 + c * 3 + d] / (nq[c] * nk[d]) * T;
        // softmax over d per row c
#pragma unroll
        for (int c = 0; c < 3; c++) {
            float mx = fmaxf(a[c][0], fmaxf(a[c][1], a[c][2]));
            float e0 = expf(a[c][0] - mx);
            float e1 = expf(a[c][1] - mx);
            float e2 = expf(a[c][2] - mx);
            float inv = 1.f / (e0 + e1 + e2);
            a[c][0] = e0 * inv; a[c][1] = e1 * inv; a[c][2] = e2 * inv;
        }
        // M[co][d] = sum_c proj_w[co][c] * a[c][d]
#pragma unroll
        for (int co = 0; co < 3; co++)
#pragma unroll
            for (int d = 0; d < 3; d++) {
                float m = 0.f;
#pragma unroll
                for (int c = 0; c < 3; c++) m += proj_w[co * 3 + c] * a[c][d];
                g_M[b][co * 3 + d] = m;
            }
    }
}

__global__ __launch_bounds__(NTH) void k_out(const float* __restrict__ x,
                                             const float* __restrict__ kC,
                                             const float* __restrict__ kD,
                                             const float* __restrict__ proj_b,
                                             float* __restrict__ out) {
    __shared__ float s[3][HY][HX];

    const int b = blockIdx.z;
    const int gx0 = blockIdx.x * TX, gy0 = blockIdx.y * TILE_Y;
    const int tid = threadIdx.x;
    const int tx = tid & 31, tg = tid >> 5;
    const int oy0 = tg * RPT;

    const float* xb = x + (size_t)b * 3 * N_PIX;

    stage1_chanlast(xb, kC, s, gx0, gy0, tid);
    __syncthreads();

    float k[3][RPT];
    dw_col(s, kD, tx, oy0, k);

    float m[9];
#pragma unroll
    for (int i = 0; i < 9; i++) m[i] = g_M[b][i];
    float b0 = proj_b[0], b1 = proj_b[1], b2 = proj_b[2];

#pragma unroll
    for (int r = 0; r < RPT; r++) {
        int gy = gy0 + oy0 + r, gx = gx0 + tx;
        size_t o = ((size_t)b * N_PIX + (size_t)gy * W_IMG + gx) * 3;
        out[o + 0] = m[0] * k[0][r] + m[1] * k[1][r] + m[2] * k[2][r] + b0;
        out[o + 1] = m[3] * k[0][r] + m[4] * k[1][r] + m[5] * k[2][r] + b1;
        out[o + 2] = m[6] * k[0][r] + m[7] * k[1][r] + m[8] * k[2][r] + b2;
    }
}

extern "C" void kernel_launch(void* const* d_in, const int* in_sizes, int n_in,
                              void* d_out, int out_size) {
    const float* x     = (const float*)d_in[0];
    const float* fhigh = (const float*)d_in[1];
    const float* qCw   = (const float*)d_in[2];
    const float* qdw   = (const float*)d_in[3];
    const float* kCw   = (const float*)d_in[4];
    const float* kdw   = (const float*)d_in[5];
    const float* projw = (const float*)d_in[6];
    const float* projb = (const float*)d_in[7];
    const float* temp  = (const float*)d_in[8];
    float* out = (float*)d_out;

    int B = in_sizes[0] / (N_PIX * 3);
    if (B > MAXB) B = MAXB;

    k_zero<<<1, 128>>>();
    dim3 grid(W_IMG / TX, W_IMG / TILE_Y, B);
    k_stats<<<grid, NTH>>>(x, fhigh, qCw, qdw, kCw, kdw);
    k_attn<<<1, 1>>>(projw, temp, B);
    k_out<<<grid, NTH>>>(x, kCw, kdw, projb, out);
}